// round 3
// baseline (speedup 1.0000x reference)
#include <cuda_runtime.h>
#include <cstdint>
#include <math.h>

#define NMAX   100000
#define EMAX   3400000
#define NFEAT  256
#define NHID   64
#define NHEADS 3
#define F1     192      // NHEADS*NHID
#define NCLASS 40

// ---------------- scratch (device globals; no allocations allowed) ----------
__device__ __align__(16) float g_h   [NMAX * F1];      // layer1 h = x@W
__device__ __align__(16) float g_out1[NMAX * F1];      // layer1 output (post elu)
__device__ __align__(16) float g_h2  [NMAX * NCLASS];  // layer2 h = out1@W_out
__device__ float g_fd  [NMAX * NHEADS];
__device__ float g_fs  [NMAX * NHEADS];
__device__ float g_f2d [NMAX];
__device__ float g_f2s [NMAX];

__device__ int   g_is64;                 // 1 if edge_index is int64, else int32
__device__ int   g_cnt    [NMAX];
__device__ int   g_rowptr [NMAX + 1];
__device__ int   g_cursor [NMAX];
__device__ int   g_csr_src[EMAX];
__device__ int   g_epos   [EMAX];
__device__ __align__(16) float g_csr_w [EMAX * 3];  // layer1 weights (3 heads)
__device__ float g_csr_w2[EMAX];                    // layer2 weights

__device__ __forceinline__ float elu1(float x) { return x > 0.f ? x : expm1f(x); }
__device__ __forceinline__ float att_w(float l) {
    float lr = l > 0.f ? l : 0.2f * l;   // leaky_relu(l, 0.2)
    return expf(-lr);
}

// read edge id at logical element index idx, given dtype flag
__device__ __forceinline__ int edge_at(const void* ei, long idx, int is64) {
    if (is64) return (int)((const long long*)ei)[idx];
    return ((const int*)ei)[idx];
}

// ---------------- dtype detection -------------------------------------------
// int64 node ids < 2^31  =>  high words (odd int32 elements) are all zero.
__global__ void detect_kernel(const int* __restrict__ ei32) {
    g_is64 = (ei32[1] == 0 && ei32[3] == 0 && ei32[5] == 0) ? 1 : 0;
}

// ---------------- CSR build --------------------------------------------------
__global__ void zero_cnt_kernel(int n) {
    int i = blockIdx.x * blockDim.x + threadIdx.x;
    if (i < n) g_cnt[i] = 0;
}

__global__ void count_kernel(const void* __restrict__ ei, int E) {
    int e = blockIdx.x * blockDim.x + threadIdx.x;
    if (e >= E) return;
    int is64 = g_is64;
    atomicAdd(&g_cnt[edge_at(ei, e, is64)], 1);
}

#define SCAN_T 1024
__global__ __launch_bounds__(SCAN_T) void scan_kernel(int n) {
    __shared__ int sh[SCAN_T];
    int t = threadIdx.x;
    int chunk = (n + SCAN_T - 1) / SCAN_T;
    int start = t * chunk;
    int end   = min(start + chunk, n);
    int sum = 0;
    for (int i = start; i < end; i++) sum += g_cnt[i];
    sh[t] = sum;
    __syncthreads();
    for (int off = 1; off < SCAN_T; off <<= 1) {
        int v = sh[t];
        int o = (t >= off) ? sh[t - off] : 0;
        __syncthreads();
        sh[t] = v + o;
        __syncthreads();
    }
    int run = (t > 0) ? sh[t - 1] : 0;   // exclusive base
    for (int i = start; i < end; i++) {
        g_rowptr[i] = run;
        g_cursor[i] = run;
        run += g_cnt[i];
    }
    if (t == SCAN_T - 1) g_rowptr[n] = run;
}

// scatter + layer1 edge weights (needs g_fd/g_fs)
__global__ void scatter_kernel(const void* __restrict__ ei, int E) {
    int e = blockIdx.x * blockDim.x + threadIdx.x;
    if (e >= E) return;
    int is64 = g_is64;
    int dst = edge_at(ei, e, is64);
    int src = edge_at(ei, (long)E + e, is64);
    int pos = atomicAdd(&g_cursor[dst], 1);
    g_csr_src[pos] = src;
    g_epos[e] = pos;
#pragma unroll
    for (int h = 0; h < 3; h++)
        g_csr_w[pos * 3 + h] = att_w(g_fd[dst * 3 + h] + g_fs[src * 3 + h]);
}

// layer2 edge weights (needs g_f2d/g_f2s, placed at CSR positions)
__global__ void weight2_kernel(const void* __restrict__ ei, int E) {
    int e = blockIdx.x * blockDim.x + threadIdx.x;
    if (e >= E) return;
    int is64 = g_is64;
    int dst = edge_at(ei, e, is64);
    int src = edge_at(ei, (long)E + e, is64);
    g_csr_w2[g_epos[e]] = att_w(g_f2d[dst] + g_f2s[src]);
}

// ---------------- GEMM1: g_h[n, head*64+c] = x @ W[head] -------------------
__global__ __launch_bounds__(256) void gemm1_kernel(
    const float* __restrict__ x, const float* __restrict__ W, int n)
{
    __shared__ float As[16][128];
    __shared__ float Bs[16][64];
    const int head = blockIdx.y;
    const int m0   = blockIdx.x * 128;
    const int tid  = threadIdx.x;
    const float* Wb = W + head * NFEAT * NHID;

    const int cx = tid & 15;
    const int ry = tid >> 4;

    float acc[8][4];
#pragma unroll
    for (int i = 0; i < 8; i++)
#pragma unroll
        for (int j = 0; j < 4; j++) acc[i][j] = 0.f;

    for (int kt = 0; kt < NFEAT; kt += 16) {
#pragma unroll
        for (int it = 0; it < 2; it++) {
            int j   = tid + it * 256;
            int row = j >> 2;
            int c4  = (j & 3) * 4;
            int gm  = m0 + row;
            float4 v = make_float4(0.f, 0.f, 0.f, 0.f);
            if (gm < n) v = *(const float4*)(x + (long)gm * NFEAT + kt + c4);
            As[c4 + 0][row] = v.x;
            As[c4 + 1][row] = v.y;
            As[c4 + 2][row] = v.z;
            As[c4 + 3][row] = v.w;
        }
        {
            int row = tid >> 4;
            int c4  = (tid & 15) * 4;
            float4 v = *(const float4*)(Wb + (kt + row) * NHID + c4);
            *(float4*)&Bs[row][c4] = v;
        }
        __syncthreads();
#pragma unroll
        for (int k = 0; k < 16; k++) {
            float4 b   = *(const float4*)&Bs[k][cx * 4];
            float4 a0  = *(const float4*)&As[k][ry * 8];
            float4 a1v = *(const float4*)&As[k][ry * 8 + 4];
            float a[8] = {a0.x, a0.y, a0.z, a0.w, a1v.x, a1v.y, a1v.z, a1v.w};
#pragma unroll
            for (int i = 0; i < 8; i++) {
                acc[i][0] += a[i] * b.x;
                acc[i][1] += a[i] * b.y;
                acc[i][2] += a[i] * b.z;
                acc[i][3] += a[i] * b.w;
            }
        }
        __syncthreads();
    }
#pragma unroll
    for (int i = 0; i < 8; i++) {
        int gm = m0 + ry * 8 + i;
        if (gm < n) {
            float4 v = make_float4(acc[i][0], acc[i][1], acc[i][2], acc[i][3]);
            *(float4*)(g_h + (long)gm * F1 + head * NHID + cx * 4) = v;
        }
    }
}

// ---------------- fdot1: per-node attention factors (warp per node) --------
__global__ __launch_bounds__(256) void fdot1_kernel(
    const float* __restrict__ a1, const float* __restrict__ a2, int n)
{
    __shared__ float s1[F1], s2[F1];
    int tid = threadIdx.x;
    if (tid < F1) { s1[tid] = a1[tid]; s2[tid] = a2[tid]; }
    __syncthreads();

    int node = blockIdx.x * 8 + (tid >> 5);
    int lane = tid & 31;
    bool valid = node < n;
    int nclamp = valid ? node : (n - 1);
    const float* hr = g_h + (long)nclamp * F1;

    float d[3], s[3];
#pragma unroll
    for (int h = 0; h < 3; h++) {
        int i0 = h * 64 + lane;
        int i1 = h * 64 + 32 + lane;
        float v0 = hr[i0], v1 = hr[i1];
        d[h] = v0 * s1[i0] + v1 * s1[i1];
        s[h] = v0 * s2[i0] + v1 * s2[i1];
    }
#pragma unroll
    for (int off = 16; off > 0; off >>= 1) {
#pragma unroll
        for (int h = 0; h < 3; h++) {
            d[h] += __shfl_xor_sync(0xffffffffu, d[h], off);
            s[h] += __shfl_xor_sync(0xffffffffu, s[h], off);
        }
    }
    if (valid && lane == 0) {
#pragma unroll
        for (int h = 0; h < 3; h++) {
            g_fd[node * 3 + h] = d[h];
            g_fs[node * 3 + h] = s[h];
        }
    }
}

// ---------------- layer1 aggregation: gather + normalize + elu -------------
// one block of 64 threads per dst node; threads 0..47 each own one float4
// feature slice (head = t/16); no atomics.
__global__ __launch_bounds__(64) void agg1_kernel(int n) {
    int node = blockIdx.x;
    if (node >= n) return;
    int t = threadIdx.x;
    int rs = g_rowptr[node];
    int re = g_rowptr[node + 1];
    bool active = t < 48;
    int head = t >> 4;

    float ax = 0.f, ay = 0.f, az = 0.f, aw = 0.f, den = 0.f;
    for (int j = rs; j < re; j++) {
        int src = g_csr_src[j];
        if (active) {
            float  w = g_csr_w[j * 3 + head];
            float4 v = *(const float4*)(g_h + (long)src * F1 + t * 4);
            ax += w * v.x; ay += w * v.y; az += w * v.z; aw += w * v.w;
            den += w;
        }
    }
    if (active) {
        float inv = 1.0f / (den + 1e-16f);
        float4 r;
        r.x = elu1(ax * inv);
        r.y = elu1(ay * inv);
        r.z = elu1(az * inv);
        r.w = elu1(aw * inv);
        *(float4*)(g_out1 + (long)node * F1 + t * 4) = r;
    }
}

// ---------------- GEMM2: g_h2 = g_out1[n,192] @ W_out[192,40] --------------
__global__ __launch_bounds__(256) void gemm2_kernel(const float* __restrict__ Wo, int n) {
    __shared__ float As[16][192];
    __shared__ float Ws[40][196];
    int tid = threadIdx.x;
    int r0  = blockIdx.x * 16;

    for (int i = tid; i < F1 * NCLASS; i += 256) {
        int k = i / NCLASS, c = i % NCLASS;
        Ws[c][k] = Wo[i];
    }
    for (int j = tid; j < 16 * 48; j += 256) {
        int row = j / 48;
        int c4  = (j % 48) * 4;
        int gm  = r0 + row;
        float4 v = make_float4(0.f, 0.f, 0.f, 0.f);
        if (gm < n) v = *(const float4*)(g_out1 + (long)gm * F1 + c4);
        *(float4*)&As[row][c4] = v;
    }
    __syncthreads();

#pragma unroll
    for (int it = 0; it < 3; it++) {
        int o = tid + it * 256;
        if (o < 16 * NCLASS) {
            int r = o / NCLASS, c = o % NCLASS;
            const float4* a4 = (const float4*)As[r];
            const float4* w4 = (const float4*)Ws[c];
            float acc = 0.f;
#pragma unroll
            for (int k = 0; k < 48; k++) {
                float4 a = a4[k], w = w4[k];
                acc += a.x * w.x + a.y * w.y + a.z * w.z + a.w * w.w;
            }
            int gm = r0 + r;
            if (gm < n) g_h2[(long)gm * NCLASS + c] = acc;
        }
    }
}

// ---------------- fdot2 ----------------------------------------------------
__global__ void fdot2_kernel(const float* __restrict__ a1o,
                             const float* __restrict__ a2o, int n)
{
    __shared__ float s1[NCLASS], s2[NCLASS];
    int tid = threadIdx.x;
    if (tid < NCLASS) { s1[tid] = a1o[tid]; s2[tid] = a2o[tid]; }
    __syncthreads();
    int node = blockIdx.x * blockDim.x + tid;
    if (node >= n) return;
    const float4* hr = (const float4*)(g_h2 + (long)node * NCLASS);
    float d = 0.f, s = 0.f;
#pragma unroll
    for (int q = 0; q < 10; q++) {
        float4 v = hr[q];
        d += v.x * s1[q * 4 + 0] + v.y * s1[q * 4 + 1] + v.z * s1[q * 4 + 2] + v.w * s1[q * 4 + 3];
        s += v.x * s2[q * 4 + 0] + v.y * s2[q * 4 + 1] + v.z * s2[q * 4 + 2] + v.w * s2[q * 4 + 3];
    }
    g_f2d[node] = d;
    g_f2s[node] = s;
}

// ---------------- layer2 aggregation: gather + normalize + final elu -------
__global__ __launch_bounds__(64) void agg2_kernel(float* __restrict__ out, int n) {
    int node = blockIdx.x;
    if (node >= n) return;
    int t = threadIdx.x;
    int rs = g_rowptr[node];
    int re = g_rowptr[node + 1];
    bool active = t < NCLASS;

    float acc = 0.f, den = 0.f;
    for (int j = rs; j < re; j++) {
        float w = g_csr_w2[j];
        if (active) {
            int src = g_csr_src[j];
            acc += w * g_h2[(long)src * NCLASS + t];
            den += w;
        }
    }
    if (active) {
        float v = acc / (den + 1e-16f);
        out[(long)node * NCLASS + t] = elu1(v);
    }
}

// ---------------- launch ---------------------------------------------------
extern "C" void kernel_launch(void* const* d_in, const int* in_sizes, int n_in,
                              void* d_out, int out_size)
{
    const float* x   = (const float*)d_in[0];
    const void*  ei  = d_in[1];
    const float* W   = (const float*)d_in[2];
    const float* a1  = (const float*)d_in[3];
    const float* a2  = (const float*)d_in[4];
    const float* Wo  = (const float*)d_in[5];
    const float* a1o = (const float*)d_in[6];
    const float* a2o = (const float*)d_in[7];
    float* out = (float*)d_out;

    int n = in_sizes[0] / NFEAT;     // 100000
    int E = in_sizes[1] / 2;         // 3300000 (element count is dtype-aware)

    detect_kernel<<<1, 1>>>((const int*)ei);

    // CSR structure build
    zero_cnt_kernel<<<(n + 1023) / 1024, 1024>>>(n);
    count_kernel<<<(E + 255) / 256, 256>>>(ei, E);
    scan_kernel<<<1, SCAN_T>>>(n);

    // layer 1 dense
    dim3 g1((n + 127) / 128, NHEADS);
    gemm1_kernel<<<g1, 256>>>(x, W, n);
    fdot1_kernel<<<(n + 7) / 8, 256>>>(a1, a2, n);

    // CSR scatter + layer1 edge weights
    scatter_kernel<<<(E + 255) / 256, 256>>>(ei, E);

    // layer1 aggregate (fused normalize+elu)
    agg1_kernel<<<n, 64>>>(n);

    // layer 2 dense
    gemm2_kernel<<<(n + 15) / 16, 256>>>(Wo, n);
    fdot2_kernel<<<(n + 255) / 256, 256>>>(a1o, a2o, n);

    // layer2 edge weights + aggregate (fused normalize + final elu)
    weight2_kernel<<<(E + 255) / 256, 256>>>(ei, E);
    agg2_kernel<<<n, 64>>>(out, n);
}

// round 4
// speedup vs baseline: 1.1393x; 1.1393x over previous
#include <cuda_runtime.h>
#include <cstdint>
#include <math.h>

#define NMAX   100000
#define EMAX   3400000
#define NFEAT  256
#define NHID   64
#define NHEADS 3
#define F1     192      // NHEADS*NHID
#define NCLASS 40

// ---------------- scratch (device globals; no allocations allowed) ----------
__device__ __align__(16) float g_h   [NMAX * F1];      // layer1 h = x@W
__device__ __align__(16) float g_out1[NMAX * F1];      // layer1 output (post elu)
__device__ __align__(16) float g_h2  [NMAX * NCLASS];  // layer2 h = out1@W_out
__device__ float g_fd  [NMAX * NHEADS];
__device__ float g_fs  [NMAX * NHEADS];
__device__ float g_f2d [NMAX];
__device__ float g_f2s [NMAX];

__device__ int   g_is64;                 // 1 if edge_index is int64, else int32
__device__ int   g_cnt    [NMAX];
__device__ int   g_rowptr [NMAX + 1];
__device__ int   g_cursor [NMAX];
__device__ int   g_part   [128];
__device__ int   g_total;
__device__ int   g_csr_src[EMAX];
__device__ int   g_epos   [EMAX];
__device__ __align__(16) float g_csr_w [EMAX * 3];  // layer1 weights (3 heads)
__device__ float g_csr_w2[EMAX];                    // layer2 weights

__device__ __forceinline__ float elu1(float x) { return x > 0.f ? x : expm1f(x); }
__device__ __forceinline__ float att_w(float l) {
    float lr = l > 0.f ? l : 0.2f * l;   // leaky_relu(l, 0.2)
    return expf(-lr);
}

__device__ __forceinline__ int edge_at(const void* ei, long idx, int is64) {
    if (is64) return (int)((const long long*)ei)[idx];
    return ((const int*)ei)[idx];
}

// ---------------- dtype detection -------------------------------------------
__global__ void detect_kernel(const int* __restrict__ ei32) {
    g_is64 = (ei32[1] == 0 && ei32[3] == 0 && ei32[5] == 0) ? 1 : 0;
}

// ---------------- CSR build --------------------------------------------------
__global__ void zero_cnt_kernel(int n) {
    int i = blockIdx.x * blockDim.x + threadIdx.x;
    if (i < n) g_cnt[i] = 0;
}

__global__ void count_kernel(const void* __restrict__ ei, int E) {
    int e = blockIdx.x * blockDim.x + threadIdx.x;
    if (e >= E) return;
    int is64 = g_is64;
    atomicAdd(&g_cnt[edge_at(ei, e, is64)], 1);
}

// --- multi-block scan: A) block-local scans, B) scan of partials, C) add base
__global__ __launch_bounds__(1024) void scanA_kernel(int n) {
    __shared__ int sh[1024];
    int t = threadIdx.x;
    int i = blockIdx.x * 1024 + t;
    int v = (i < n) ? g_cnt[i] : 0;
    sh[t] = v;
    __syncthreads();
#pragma unroll
    for (int off = 1; off < 1024; off <<= 1) {
        int x = sh[t];
        int y = (t >= off) ? sh[t - off] : 0;
        __syncthreads();
        sh[t] = x + y;
        __syncthreads();
    }
    if (i < n) g_rowptr[i] = sh[t] - v;       // block-local exclusive
    if (t == 1023) g_part[blockIdx.x] = sh[1023];
}

__global__ __launch_bounds__(128) void scanB_kernel(int nb) {
    __shared__ int sh[128];
    int t = threadIdx.x;
    int v = (t < nb) ? g_part[t] : 0;
    sh[t] = v;
    __syncthreads();
#pragma unroll
    for (int off = 1; off < 128; off <<= 1) {
        int x = sh[t];
        int y = (t >= off) ? sh[t - off] : 0;
        __syncthreads();
        sh[t] = x + y;
        __syncthreads();
    }
    g_part[t] = sh[t] - v;                    // exclusive base
    if (t == 127) g_total = sh[127];
}

__global__ __launch_bounds__(1024) void scanC_kernel(int n) {
    int i = blockIdx.x * 1024 + threadIdx.x;
    if (i < n) {
        int r = g_rowptr[i] + g_part[blockIdx.x];
        g_rowptr[i] = r;
        g_cursor[i] = r;
    }
    if (i == 0) g_rowptr[n] = g_total;
}

// scatter + layer1 edge weights (needs g_fd/g_fs)
__global__ void scatter_kernel(const void* __restrict__ ei, int E) {
    int e = blockIdx.x * blockDim.x + threadIdx.x;
    if (e >= E) return;
    int is64 = g_is64;
    int dst = edge_at(ei, e, is64);
    int src = edge_at(ei, (long)E + e, is64);
    int pos = atomicAdd(&g_cursor[dst], 1);
    g_csr_src[pos] = src;
    g_epos[e] = pos;
#pragma unroll
    for (int h = 0; h < 3; h++)
        g_csr_w[pos * 3 + h] = att_w(g_fd[dst * 3 + h] + g_fs[src * 3 + h]);
}

// layer2 edge weights
__global__ void weight2_kernel(const void* __restrict__ ei, int E) {
    int e = blockIdx.x * blockDim.x + threadIdx.x;
    if (e >= E) return;
    int is64 = g_is64;
    int dst = edge_at(ei, e, is64);
    int src = edge_at(ei, (long)E + e, is64);
    g_csr_w2[g_epos[e]] = att_w(g_f2d[dst] + g_f2s[src]);
}

// ---------------- GEMM1: g_h[n, head*64+c] = x @ W[head] -------------------
__global__ __launch_bounds__(256) void gemm1_kernel(
    const float* __restrict__ x, const float* __restrict__ W, int n)
{
    __shared__ float As[16][128];
    __shared__ float Bs[16][64];
    const int head = blockIdx.y;
    const int m0   = blockIdx.x * 128;
    const int tid  = threadIdx.x;
    const float* Wb = W + head * NFEAT * NHID;

    const int cx = tid & 15;
    const int ry = tid >> 4;

    float acc[8][4];
#pragma unroll
    for (int i = 0; i < 8; i++)
#pragma unroll
        for (int j = 0; j < 4; j++) acc[i][j] = 0.f;

    for (int kt = 0; kt < NFEAT; kt += 16) {
#pragma unroll
        for (int it = 0; it < 2; it++) {
            int j   = tid + it * 256;
            int row = j >> 2;
            int c4  = (j & 3) * 4;
            int gm  = m0 + row;
            float4 v = make_float4(0.f, 0.f, 0.f, 0.f);
            if (gm < n) v = *(const float4*)(x + (long)gm * NFEAT + kt + c4);
            As[c4 + 0][row] = v.x;
            As[c4 + 1][row] = v.y;
            As[c4 + 2][row] = v.z;
            As[c4 + 3][row] = v.w;
        }
        {
            int row = tid >> 4;
            int c4  = (tid & 15) * 4;
            float4 v = *(const float4*)(Wb + (kt + row) * NHID + c4);
            *(float4*)&Bs[row][c4] = v;
        }
        __syncthreads();
#pragma unroll
        for (int k = 0; k < 16; k++) {
            float4 b   = *(const float4*)&Bs[k][cx * 4];
            float4 a0  = *(const float4*)&As[k][ry * 8];
            float4 a1v = *(const float4*)&As[k][ry * 8 + 4];
            float a[8] = {a0.x, a0.y, a0.z, a0.w, a1v.x, a1v.y, a1v.z, a1v.w};
#pragma unroll
            for (int i = 0; i < 8; i++) {
                acc[i][0] += a[i] * b.x;
                acc[i][1] += a[i] * b.y;
                acc[i][2] += a[i] * b.z;
                acc[i][3] += a[i] * b.w;
            }
        }
        __syncthreads();
    }
#pragma unroll
    for (int i = 0; i < 8; i++) {
        int gm = m0 + ry * 8 + i;
        if (gm < n) {
            float4 v = make_float4(acc[i][0], acc[i][1], acc[i][2], acc[i][3]);
            *(float4*)(g_h + (long)gm * F1 + head * NHID + cx * 4) = v;
        }
    }
}

// ---------------- fdot1 ----------------------------------------------------
__global__ __launch_bounds__(256) void fdot1_kernel(
    const float* __restrict__ a1, const float* __restrict__ a2, int n)
{
    __shared__ float s1[F1], s2[F1];
    int tid = threadIdx.x;
    if (tid < F1) { s1[tid] = a1[tid]; s2[tid] = a2[tid]; }
    __syncthreads();

    int node = blockIdx.x * 8 + (tid >> 5);
    int lane = tid & 31;
    bool valid = node < n;
    int nclamp = valid ? node : (n - 1);
    const float* hr = g_h + (long)nclamp * F1;

    float d[3], s[3];
#pragma unroll
    for (int h = 0; h < 3; h++) {
        int i0 = h * 64 + lane;
        int i1 = h * 64 + 32 + lane;
        float v0 = hr[i0], v1 = hr[i1];
        d[h] = v0 * s1[i0] + v1 * s1[i1];
        s[h] = v0 * s2[i0] + v1 * s2[i1];
    }
#pragma unroll
    for (int off = 16; off > 0; off >>= 1) {
#pragma unroll
        for (int h = 0; h < 3; h++) {
            d[h] += __shfl_xor_sync(0xffffffffu, d[h], off);
            s[h] += __shfl_xor_sync(0xffffffffu, s[h], off);
        }
    }
    if (valid && lane == 0) {
#pragma unroll
        for (int h = 0; h < 3; h++) {
            g_fd[node * 3 + h] = d[h];
            g_fs[node * 3 + h] = s[h];
        }
    }
}

// ---------------- layer1 aggregation: gather + normalize + elu -------------
__global__ __launch_bounds__(64) void agg1_kernel(int n) {
    int node = blockIdx.x;
    if (node >= n) return;
    int t = threadIdx.x;
    int rs = g_rowptr[node];
    int re = g_rowptr[node + 1];
    bool active = t < 48;
    int head = t >> 4;

    float ax = 0.f, ay = 0.f, az = 0.f, aw = 0.f, den = 0.f;
    int j = rs;
    for (; j + 1 < re; j += 2) {
        int s0 = g_csr_src[j];
        int s1 = g_csr_src[j + 1];
        if (active) {
            float  w0 = g_csr_w[j * 3 + head];
            float  w1 = g_csr_w[(j + 1) * 3 + head];
            float4 v0 = *(const float4*)(g_h + (long)s0 * F1 + t * 4);
            float4 v1 = *(const float4*)(g_h + (long)s1 * F1 + t * 4);
            ax += w0 * v0.x + w1 * v1.x;
            ay += w0 * v0.y + w1 * v1.y;
            az += w0 * v0.z + w1 * v1.z;
            aw += w0 * v0.w + w1 * v1.w;
            den += w0 + w1;
        }
    }
    if (j < re) {
        int s0 = g_csr_src[j];
        if (active) {
            float  w = g_csr_w[j * 3 + head];
            float4 v = *(const float4*)(g_h + (long)s0 * F1 + t * 4);
            ax += w * v.x; ay += w * v.y; az += w * v.z; aw += w * v.w;
            den += w;
        }
    }
    if (active) {
        float inv = 1.0f / (den + 1e-16f);
        float4 r;
        r.x = elu1(ax * inv);
        r.y = elu1(ay * inv);
        r.z = elu1(az * inv);
        r.w = elu1(aw * inv);
        *(float4*)(g_out1 + (long)node * F1 + t * 4) = r;
    }
}

// ---------------- GEMM2: g_h2 = g_out1[n,192] @ W_out[192,40] --------------
__global__ __launch_bounds__(256) void gemm2_kernel(const float* __restrict__ Wo, int n) {
    __shared__ float As[16][192];
    __shared__ float Ws[40][196];
    int tid = threadIdx.x;
    int r0  = blockIdx.x * 16;

    for (int i = tid; i < F1 * NCLASS; i += 256) {
        int k = i / NCLASS, c = i % NCLASS;
        Ws[c][k] = Wo[i];
    }
    for (int j = tid; j < 16 * 48; j += 256) {
        int row = j / 48;
        int c4  = (j % 48) * 4;
        int gm  = r0 + row;
        float4 v = make_float4(0.f, 0.f, 0.f, 0.f);
        if (gm < n) v = *(const float4*)(g_out1 + (long)gm * F1 + c4);
        *(float4*)&As[row][c4] = v;
    }
    __syncthreads();

#pragma unroll
    for (int it = 0; it < 3; it++) {
        int o = tid + it * 256;
        if (o < 16 * NCLASS) {
            int r = o / NCLASS, c = o % NCLASS;
            const float4* a4 = (const float4*)As[r];
            const float4* w4 = (const float4*)Ws[c];
            float acc = 0.f;
#pragma unroll
            for (int k = 0; k < 48; k++) {
                float4 a = a4[k], w = w4[k];
                acc += a.x * w.x + a.y * w.y + a.z * w.z + a.w * w.w;
            }
            int gm = r0 + r;
            if (gm < n) g_h2[(long)gm * NCLASS + c] = acc;
        }
    }
}

// ---------------- fdot2 ----------------------------------------------------
__global__ void fdot2_kernel(const float* __restrict__ a1o,
                             const float* __restrict__ a2o, int n)
{
    __shared__ float s1[NCLASS], s2[NCLASS];
    int tid = threadIdx.x;
    if (tid < NCLASS) { s1[tid] = a1o[tid]; s2[tid] = a2o[tid]; }
    __syncthreads();
    int node = blockIdx.x * blockDim.x + tid;
    if (node >= n) return;
    const float4* hr = (const float4*)(g_h2 + (long)node * NCLASS);
    float d = 0.f, s = 0.f;
#pragma unroll
    for (int q = 0; q < 10; q++) {
        float4 v = hr[q];
        d += v.x * s1[q * 4 + 0] + v.y * s1[q * 4 + 1] + v.z * s1[q * 4 + 2] + v.w * s1[q * 4 + 3];
        s += v.x * s2[q * 4 + 0] + v.y * s2[q * 4 + 1] + v.z * s2[q * 4 + 2] + v.w * s2[q * 4 + 3];
    }
    g_f2d[node] = d;
    g_f2s[node] = s;
}

// ---------------- layer2 aggregation ---------------------------------------
__global__ __launch_bounds__(64) void agg2_kernel(float* __restrict__ out, int n) {
    int node = blockIdx.x;
    if (node >= n) return;
    int t = threadIdx.x;
    int rs = g_rowptr[node];
    int re = g_rowptr[node + 1];
    bool active = t < NCLASS;

    float acc = 0.f, den = 0.f;
    int j = rs;
    for (; j + 1 < re; j += 2) {
        float w0 = g_csr_w2[j];
        float w1 = g_csr_w2[j + 1];
        int s0 = g_csr_src[j];
        int s1 = g_csr_src[j + 1];
        if (active) {
            acc += w0 * g_h2[(long)s0 * NCLASS + t] + w1 * g_h2[(long)s1 * NCLASS + t];
            den += w0 + w1;
        }
    }
    if (j < re) {
        float w = g_csr_w2[j];
        int s0 = g_csr_src[j];
        if (active) {
            acc += w * g_h2[(long)s0 * NCLASS + t];
            den += w;
        }
    }
    if (active) {
        float v = acc / (den + 1e-16f);
        out[(long)node * NCLASS + t] = elu1(v);
    }
}

// ---------------- launch ---------------------------------------------------
extern "C" void kernel_launch(void* const* d_in, const int* in_sizes, int n_in,
                              void* d_out, int out_size)
{
    const float* x   = (const float*)d_in[0];
    const void*  ei  = d_in[1];
    const float* W   = (const float*)d_in[2];
    const float* a1  = (const float*)d_in[3];
    const float* a2  = (const float*)d_in[4];
    const float* Wo  = (const float*)d_in[5];
    const float* a1o = (const float*)d_in[6];
    const float* a2o = (const float*)d_in[7];
    float* out = (float*)d_out;

    int n = in_sizes[0] / NFEAT;     // 100000
    int E = in_sizes[1] / 2;         // 3300000
    int nb = (n + 1023) / 1024;      // scan blocks (98 <= 128)

    detect_kernel<<<1, 1>>>((const int*)ei);

    // CSR structure build
    zero_cnt_kernel<<<(n + 1023) / 1024, 1024>>>(n);
    count_kernel<<<(E + 255) / 256, 256>>>(ei, E);
    scanA_kernel<<<nb, 1024>>>(n);
    scanB_kernel<<<1, 128>>>(nb);
    scanC_kernel<<<nb, 1024>>>(n);

    // layer 1 dense
    dim3 g1((n + 127) / 128, NHEADS);
    gemm1_kernel<<<g1, 256>>>(x, W, n);
    fdot1_kernel<<<(n + 7) / 8, 256>>>(a1, a2, n);

    // CSR scatter + layer1 edge weights
    scatter_kernel<<<(E + 255) / 256, 256>>>(ei, E);

    // layer1 aggregate (fused normalize+elu)
    agg1_kernel<<<n, 64>>>(n);

    // layer 2 dense
    gemm2_kernel<<<(n + 15) / 16, 256>>>(Wo, n);
    fdot2_kernel<<<(n + 255) / 256, 256>>>(a1o, a2o, n);

    // layer2 edge weights + aggregate (fused normalize + final elu)
    weight2_kernel<<<(E + 255) / 256, 256>>>(ei, E);
    agg2_kernel<<<n, 64>>>(out, n);
}

// round 5
// speedup vs baseline: 1.2554x; 1.1019x over previous
#include <cuda_runtime.h>
#include <cstdint>
#include <math.h>

#define NMAX   100000
#define EMAX   3400000
#define NFEAT  256
#define NHID   64
#define NHEADS 3
#define F1     192      // NHEADS*NHID
#define NCLASS 40

// ---------------- scratch (device globals; no allocations allowed) ----------
__device__ __align__(16) float g_h   [NMAX * F1];      // layer1 h = x@W
__device__ __align__(16) float g_out1[NMAX * F1];      // layer1 output (post elu)
__device__ __align__(16) float g_h2  [NMAX * NCLASS];  // layer2 h = out1@W_out
__device__ float g_fd  [NMAX * NHEADS];
__device__ float g_fs  [NMAX * NHEADS];
__device__ float g_f2d [NMAX];
__device__ float g_f2s [NMAX];

__device__ int   g_is64;                 // 1 if edge_index is int64, else int32
__device__ int   g_cnt    [NMAX];
__device__ int   g_rowptr [NMAX + 1];
__device__ int   g_cursor [NMAX];
__device__ int   g_part   [128];
__device__ int   g_total;
__device__ int   g_csr_src[EMAX];
__device__ int   g_epos   [EMAX];
__device__ __align__(16) float g_csr_w [EMAX * 3];  // layer1 weights (3 heads)
__device__ float g_csr_w2[EMAX];                    // layer2 weights

__device__ __forceinline__ float elu1(float x) { return x > 0.f ? x : expm1f(x); }
__device__ __forceinline__ float att_w(float l) {
    float lr = l > 0.f ? l : 0.2f * l;   // leaky_relu(l, 0.2)
    return expf(-lr);
}

__device__ __forceinline__ int edge_at(const void* ei, long idx, int is64) {
    if (is64) return (int)((const long long*)ei)[idx];
    return ((const int*)ei)[idx];
}

__device__ __forceinline__ float tf32r(float x) {
    float r;
    asm("cvt.rna.tf32.f32 %0, %1;" : "=f"(r) : "f"(x));
    return r;
}

// ---------------- dtype detection -------------------------------------------
__global__ void detect_kernel(const int* __restrict__ ei32) {
    g_is64 = (ei32[1] == 0 && ei32[3] == 0 && ei32[5] == 0) ? 1 : 0;
}

// ---------------- CSR build --------------------------------------------------
__global__ void zero_cnt_kernel(int n) {
    int i = blockIdx.x * blockDim.x + threadIdx.x;
    if (i < n) g_cnt[i] = 0;
}

__global__ void count_kernel(const void* __restrict__ ei, int E) {
    int e = blockIdx.x * blockDim.x + threadIdx.x;
    if (e >= E) return;
    int is64 = g_is64;
    atomicAdd(&g_cnt[edge_at(ei, e, is64)], 1);
}

// --- multi-block scan
__global__ __launch_bounds__(1024) void scanA_kernel(int n) {
    __shared__ int sh[1024];
    int t = threadIdx.x;
    int i = blockIdx.x * 1024 + t;
    int v = (i < n) ? g_cnt[i] : 0;
    sh[t] = v;
    __syncthreads();
#pragma unroll
    for (int off = 1; off < 1024; off <<= 1) {
        int x = sh[t];
        int y = (t >= off) ? sh[t - off] : 0;
        __syncthreads();
        sh[t] = x + y;
        __syncthreads();
    }
    if (i < n) g_rowptr[i] = sh[t] - v;       // block-local exclusive
    if (t == 1023) g_part[blockIdx.x] = sh[1023];
}

__global__ __launch_bounds__(128) void scanB_kernel(int nb) {
    __shared__ int sh[128];
    int t = threadIdx.x;
    int v = (t < nb) ? g_part[t] : 0;
    sh[t] = v;
    __syncthreads();
#pragma unroll
    for (int off = 1; off < 128; off <<= 1) {
        int x = sh[t];
        int y = (t >= off) ? sh[t - off] : 0;
        __syncthreads();
        sh[t] = x + y;
        __syncthreads();
    }
    g_part[t] = sh[t] - v;                    // exclusive base
    if (t == 127) g_total = sh[127];
}

__global__ __launch_bounds__(1024) void scanC_kernel(int n) {
    int i = blockIdx.x * 1024 + threadIdx.x;
    if (i < n) {
        int r = g_rowptr[i] + g_part[blockIdx.x];
        g_rowptr[i] = r;
        g_cursor[i] = r;
    }
    if (i == 0) g_rowptr[n] = g_total;
}

// scatter + layer1 edge weights
__global__ void scatter_kernel(const void* __restrict__ ei, int E) {
    int e = blockIdx.x * blockDim.x + threadIdx.x;
    if (e >= E) return;
    int is64 = g_is64;
    int dst = edge_at(ei, e, is64);
    int src = edge_at(ei, (long)E + e, is64);
    int pos = atomicAdd(&g_cursor[dst], 1);
    g_csr_src[pos] = src;
    g_epos[e] = pos;
#pragma unroll
    for (int h = 0; h < 3; h++)
        g_csr_w[pos * 3 + h] = att_w(g_fd[dst * 3 + h] + g_fs[src * 3 + h]);
}

// layer2 edge weights
__global__ void weight2_kernel(const void* __restrict__ ei, int E) {
    int e = blockIdx.x * blockDim.x + threadIdx.x;
    if (e >= E) return;
    int is64 = g_is64;
    int dst = edge_at(ei, e, is64);
    int src = edge_at(ei, (long)E + e, is64);
    g_csr_w2[g_epos[e]] = att_w(g_f2d[dst] + g_f2s[src]);
}

// ---------------- GEMM1 (tf32 tensor cores) --------------------------------
// g_h[n, head*64+c] = x[n,256] @ W[head][256,64]
// Block: 128x64 output tile, 256 threads (8 warps as 4x2), K-tile 32.
// mma.sync.aligned.m16n8k8.row.col.f32.tf32.tf32.f32
#define AS_S 36   // A smem row stride (floats): bank-conflict-free fragments
#define BS_S 72   // B smem row stride
__global__ __launch_bounds__(256) void gemm1_tc_kernel(
    const float* __restrict__ x, const float* __restrict__ W, int n)
{
    __shared__ float As[128 * AS_S];   // [m][k]
    __shared__ float Bs[32 * BS_S];    // [k][n]

    const int head = blockIdx.y;
    const int m0   = blockIdx.x * 128;
    const int tid  = threadIdx.x;
    const float* Wb = W + head * NFEAT * NHID;

    const int wid   = tid >> 5;
    const int lane  = tid & 31;
    const int warpM = wid & 3;         // 0..3 -> 32 rows each
    const int warpN = wid >> 2;        // 0..1 -> 32 cols each
    const int g     = lane >> 2;       // 0..7
    const int tg    = lane & 3;        // 0..3

    float c[2][4][4];                  // [mtile][ntile][reg]
#pragma unroll
    for (int mt = 0; mt < 2; mt++)
#pragma unroll
        for (int nt = 0; nt < 4; nt++)
#pragma unroll
            for (int r = 0; r < 4; r++) c[mt][nt][r] = 0.f;

    for (int kt = 0; kt < NFEAT; kt += 32) {
        // load A tile 128x32: 1024 float4, 4 per thread (tf32-rounded)
#pragma unroll
        for (int it = 0; it < 4; it++) {
            int j   = tid + it * 256;
            int row = j >> 3;
            int c4  = (j & 7) * 4;
            int gm  = m0 + row;
            float4 v = make_float4(0.f, 0.f, 0.f, 0.f);
            if (gm < n) v = *(const float4*)(x + (long)gm * NFEAT + kt + c4);
            v.x = tf32r(v.x); v.y = tf32r(v.y); v.z = tf32r(v.z); v.w = tf32r(v.w);
            *(float4*)&As[row * AS_S + c4] = v;
        }
        // load B tile 32x64: 512 float4, 2 per thread (tf32-rounded)
#pragma unroll
        for (int it = 0; it < 2; it++) {
            int j   = tid + it * 256;
            int row = j >> 4;
            int c4  = (j & 15) * 4;
            float4 v = *(const float4*)(Wb + (kt + row) * NHID + c4);
            v.x = tf32r(v.x); v.y = tf32r(v.y); v.z = tf32r(v.z); v.w = tf32r(v.w);
            *(float4*)&Bs[row * BS_S + c4] = v;
        }
        __syncthreads();

#pragma unroll
        for (int ks = 0; ks < 4; ks++) {
            const int k0 = ks * 8;
            // A fragments: 2 m-tiles
            uint32_t a[2][4];
#pragma unroll
            for (int mt = 0; mt < 2; mt++) {
                int rbase = warpM * 32 + mt * 16;
                a[mt][0] = __float_as_uint(As[(rbase + g)     * AS_S + k0 + tg]);
                a[mt][1] = __float_as_uint(As[(rbase + g + 8) * AS_S + k0 + tg]);
                a[mt][2] = __float_as_uint(As[(rbase + g)     * AS_S + k0 + tg + 4]);
                a[mt][3] = __float_as_uint(As[(rbase + g + 8) * AS_S + k0 + tg + 4]);
            }
            // B fragments: 4 n-tiles
            uint32_t b[4][2];
#pragma unroll
            for (int nt = 0; nt < 4; nt++) {
                int cbase = warpN * 32 + nt * 8;
                b[nt][0] = __float_as_uint(Bs[(k0 + tg)     * BS_S + cbase + g]);
                b[nt][1] = __float_as_uint(Bs[(k0 + tg + 4) * BS_S + cbase + g]);
            }
#pragma unroll
            for (int mt = 0; mt < 2; mt++)
#pragma unroll
                for (int nt = 0; nt < 4; nt++) {
                    asm volatile(
                        "mma.sync.aligned.m16n8k8.row.col.f32.tf32.tf32.f32 "
                        "{%0,%1,%2,%3}, {%4,%5,%6,%7}, {%8,%9}, {%0,%1,%2,%3};"
                        : "+f"(c[mt][nt][0]), "+f"(c[mt][nt][1]),
                          "+f"(c[mt][nt][2]), "+f"(c[mt][nt][3])
                        : "r"(a[mt][0]), "r"(a[mt][1]), "r"(a[mt][2]), "r"(a[mt][3]),
                          "r"(b[nt][0]), "r"(b[nt][1]));
                }
        }
        __syncthreads();
    }

    // epilogue: write c -> g_h
#pragma unroll
    for (int mt = 0; mt < 2; mt++) {
        int row0 = m0 + warpM * 32 + mt * 16 + g;
#pragma unroll
        for (int nt = 0; nt < 4; nt++) {
            int col = head * NHID + warpN * 32 + nt * 8 + tg * 2;
            if (row0 < n)
                *(float2*)(g_h + (long)row0 * F1 + col) = make_float2(c[mt][nt][0], c[mt][nt][1]);
            if (row0 + 8 < n)
                *(float2*)(g_h + (long)(row0 + 8) * F1 + col) = make_float2(c[mt][nt][2], c[mt][nt][3]);
        }
    }
}

// ---------------- fdot1 ----------------------------------------------------
__global__ __launch_bounds__(256) void fdot1_kernel(
    const float* __restrict__ a1, const float* __restrict__ a2, int n)
{
    __shared__ float s1[F1], s2[F1];
    int tid = threadIdx.x;
    if (tid < F1) { s1[tid] = a1[tid]; s2[tid] = a2[tid]; }
    __syncthreads();

    int node = blockIdx.x * 8 + (tid >> 5);
    int lane = tid & 31;
    bool valid = node < n;
    int nclamp = valid ? node : (n - 1);
    const float* hr = g_h + (long)nclamp * F1;

    float d[3], s[3];
#pragma unroll
    for (int h = 0; h < 3; h++) {
        int i0 = h * 64 + lane;
        int i1 = h * 64 + 32 + lane;
        float v0 = hr[i0], v1 = hr[i1];
        d[h] = v0 * s1[i0] + v1 * s1[i1];
        s[h] = v0 * s2[i0] + v1 * s2[i1];
    }
#pragma unroll
    for (int off = 16; off > 0; off >>= 1) {
#pragma unroll
        for (int h = 0; h < 3; h++) {
            d[h] += __shfl_xor_sync(0xffffffffu, d[h], off);
            s[h] += __shfl_xor_sync(0xffffffffu, s[h], off);
        }
    }
    if (valid && lane == 0) {
#pragma unroll
        for (int h = 0; h < 3; h++) {
            g_fd[node * 3 + h] = d[h];
            g_fs[node * 3 + h] = s[h];
        }
    }
}

// ---------------- layer1 aggregation ---------------------------------------
__global__ __launch_bounds__(64) void agg1_kernel(int n) {
    int node = blockIdx.x;
    if (node >= n) return;
    int t = threadIdx.x;
    int rs = g_rowptr[node];
    int re = g_rowptr[node + 1];
    bool active = t < 48;
    int head = t >> 4;

    float ax = 0.f, ay = 0.f, az = 0.f, aw = 0.f, den = 0.f;
    int j = rs;
    for (; j + 1 < re; j += 2) {
        int s0 = g_csr_src[j];
        int s1 = g_csr_src[j + 1];
        if (active) {
            float  w0 = g_csr_w[j * 3 + head];
            float  w1 = g_csr_w[(j + 1) * 3 + head];
            float4 v0 = *(const float4*)(g_h + (long)s0 * F1 + t * 4);
            float4 v1 = *(const float4*)(g_h + (long)s1 * F1 + t * 4);
            ax += w0 * v0.x + w1 * v1.x;
            ay += w0 * v0.y + w1 * v1.y;
            az += w0 * v0.z + w1 * v1.z;
            aw += w0 * v0.w + w1 * v1.w;
            den += w0 + w1;
        }
    }
    if (j < re) {
        int s0 = g_csr_src[j];
        if (active) {
            float  w = g_csr_w[j * 3 + head];
            float4 v = *(const float4*)(g_h + (long)s0 * F1 + t * 4);
            ax += w * v.x; ay += w * v.y; az += w * v.z; aw += w * v.w;
            den += w;
        }
    }
    if (active) {
        float inv = 1.0f / (den + 1e-16f);
        float4 r;
        r.x = elu1(ax * inv);
        r.y = elu1(ay * inv);
        r.z = elu1(az * inv);
        r.w = elu1(aw * inv);
        *(float4*)(g_out1 + (long)node * F1 + t * 4) = r;
    }
}

// ---------------- GEMM2: g_h2 = g_out1[n,192] @ W_out[192,40] --------------
__global__ __launch_bounds__(256) void gemm2_kernel(const float* __restrict__ Wo, int n) {
    __shared__ float As2[16][192];
    __shared__ float Ws[40][196];
    int tid = threadIdx.x;
    int r0  = blockIdx.x * 16;

    for (int i = tid; i < F1 * NCLASS; i += 256) {
        int k = i / NCLASS, c = i % NCLASS;
        Ws[c][k] = Wo[i];
    }
    for (int j = tid; j < 16 * 48; j += 256) {
        int row = j / 48;
        int c4  = (j % 48) * 4;
        int gm  = r0 + row;
        float4 v = make_float4(0.f, 0.f, 0.f, 0.f);
        if (gm < n) v = *(const float4*)(g_out1 + (long)gm * F1 + c4);
        *(float4*)&As2[row][c4] = v;
    }
    __syncthreads();

#pragma unroll
    for (int it = 0; it < 3; it++) {
        int o = tid + it * 256;
        if (o < 16 * NCLASS) {
            int r = o / NCLASS, c = o % NCLASS;
            const float4* a4 = (const float4*)As2[r];
            const float4* w4 = (const float4*)Ws[c];
            float acc = 0.f;
#pragma unroll
            for (int k = 0; k < 48; k++) {
                float4 a = a4[k], w = w4[k];
                acc += a.x * w.x + a.y * w.y + a.z * w.z + a.w * w.w;
            }
            int gm = r0 + r;
            if (gm < n) g_h2[(long)gm * NCLASS + c] = acc;
        }
    }
}

// ---------------- fdot2 ----------------------------------------------------
__global__ void fdot2_kernel(const float* __restrict__ a1o,
                             const float* __restrict__ a2o, int n)
{
    __shared__ float s1[NCLASS], s2[NCLASS];
    int tid = threadIdx.x;
    if (tid < NCLASS) { s1[tid] = a1o[tid]; s2[tid] = a2o[tid]; }
    __syncthreads();
    int node = blockIdx.x * blockDim.x + tid;
    if (node >= n) return;
    const float4* hr = (const float4*)(g_h2 + (long)node * NCLASS);
    float d = 0.f, s = 0.f;
#pragma unroll
    for (int q = 0; q < 10; q++) {
        float4 v = hr[q];
        d += v.x * s1[q * 4 + 0] + v.y * s1[q * 4 + 1] + v.z * s1[q * 4 + 2] + v.w * s1[q * 4 + 3];
        s += v.x * s2[q * 4 + 0] + v.y * s2[q * 4 + 1] + v.z * s2[q * 4 + 2] + v.w * s2[q * 4 + 3];
    }
    g_f2d[node] = d;
    g_f2s[node] = s;
}

// ---------------- layer2 aggregation ---------------------------------------
__global__ __launch_bounds__(64) void agg2_kernel(float* __restrict__ out, int n) {
    int node = blockIdx.x;
    if (node >= n) return;
    int t = threadIdx.x;
    int rs = g_rowptr[node];
    int re = g_rowptr[node + 1];
    bool active = t < NCLASS;

    float acc = 0.f, den = 0.f;
    int j = rs;
    for (; j + 1 < re; j += 2) {
        float w0 = g_csr_w2[j];
        float w1 = g_csr_w2[j + 1];
        int s0 = g_csr_src[j];
        int s1 = g_csr_src[j + 1];
        if (active) {
            acc += w0 * g_h2[(long)s0 * NCLASS + t] + w1 * g_h2[(long)s1 * NCLASS + t];
            den += w0 + w1;
        }
    }
    if (j < re) {
        float w = g_csr_w2[j];
        int s0 = g_csr_src[j];
        if (active) {
            acc += w * g_h2[(long)s0 * NCLASS + t];
            den += w;
        }
    }
    if (active) {
        float v = acc / (den + 1e-16f);
        out[(long)node * NCLASS + t] = elu1(v);
    }
}

// ---------------- launch ---------------------------------------------------
extern "C" void kernel_launch(void* const* d_in, const int* in_sizes, int n_in,
                              void* d_out, int out_size)
{
    const float* x   = (const float*)d_in[0];
    const void*  ei  = d_in[1];
    const float* W   = (const float*)d_in[2];
    const float* a1  = (const float*)d_in[3];
    const float* a2  = (const float*)d_in[4];
    const float* Wo  = (const float*)d_in[5];
    const float* a1o = (const float*)d_in[6];
    const float* a2o = (const float*)d_in[7];
    float* out = (float*)d_out;

    int n = in_sizes[0] / NFEAT;     // 100000
    int E = in_sizes[1] / 2;         // 3300000
    int nb = (n + 1023) / 1024;      // scan blocks (98 <= 128)

    detect_kernel<<<1, 1>>>((const int*)ei);

    // CSR structure build
    zero_cnt_kernel<<<(n + 1023) / 1024, 1024>>>(n);
    count_kernel<<<(E + 255) / 256, 256>>>(ei, E);
    scanA_kernel<<<nb, 1024>>>(n);
    scanB_kernel<<<1, 128>>>(nb);
    scanC_kernel<<<nb, 1024>>>(n);

    // layer 1 dense
    dim3 g1((n + 127) / 128, NHEADS);
    gemm1_tc_kernel<<<g1, 256>>>(x, W, n);
    fdot1_kernel<<<(n + 7) / 8, 256>>>(a1, a2, n);

    // CSR scatter + layer1 edge weights
    scatter_kernel<<<(E + 255) / 256, 256>>>(ei, E);

    // layer1 aggregate (fused normalize+elu)
    agg1_kernel<<<n, 64>>>(n);

    // layer 2 dense
    gemm2_kernel<<<(n + 15) / 16, 256>>>(Wo, n);
    fdot2_kernel<<<(n + 255) / 256, 256>>>(a1o, a2o, n);

    // layer2 edge weights + aggregate (fused normalize + final elu)
    weight2_kernel<<<(E + 255) / 256, 256>>>(ei, E);
    agg2_kernel<<<n, 64>>>(out, n);
}